// round 6
// baseline (speedup 1.0000x reference)
#include <cuda_runtime.h>
#include <cstdint>

#define N_NODES_MAX 100000
#define N_EDGES_MAX 1600000

// ---------------- device scratch (no allocations allowed) ----------------
__device__ float g_h[(size_t)N_NODES_MAX * 128];
__device__ float g_y[(size_t)N_NODES_MAX * 128];
__device__ float g_dinv[N_NODES_MAX];
__device__ int   g_count[N_NODES_MAX];
__device__ int   g_fill[N_NODES_MAX];
__device__ int   g_rowptr[N_NODES_MAX + 1];
__device__ int   g_esrc[N_EDGES_MAX];
__device__ float g_enorm[N_EDGES_MAX];
__device__ int   g_bsums[256];
__device__ int   g_is32;
// transposed tf32-rounded weights: WT[n][k]
__device__ float g_wt1[128 * 384];
__device__ float g_wt2[128 * 128];
__device__ float g_wt3[128 * 128];
__device__ float g_wt4[128 * 128];
__device__ float g_wt5[64 * 128];

// ---------------- helpers ----------------
__device__ __forceinline__ int edge_val(const void* ei, int is32, long long idx) {
    if (is32) return ((const int*)ei)[idx];
    return (int)((const long long*)ei)[idx];
}
__device__ __forceinline__ uint32_t to_tf32(float f) {
    uint32_t r;
    asm("cvt.rna.tf32.f32 %0, %1;" : "=r"(r) : "f"(f));
    return r;
}
__device__ __forceinline__ float round_tf32(float f) {
    return __uint_as_float(to_tf32(f));
}
__device__ __forceinline__ void cp_async16(uint32_t dst, const void* src, int srcsize) {
    asm volatile("cp.async.ca.shared.global [%0], [%1], 16, %2;"
                 :: "r"(dst), "l"(src), "r"(srcsize));
}
__device__ __forceinline__ void cp_commit() { asm volatile("cp.async.commit_group;"); }
template<int N>
__device__ __forceinline__ void cp_wait() { asm volatile("cp.async.wait_group %0;" :: "n"(N)); }

__device__ __forceinline__ void ldsm_x4(uint32_t& r0, uint32_t& r1, uint32_t& r2, uint32_t& r3,
                                        uint32_t addr) {
    asm volatile("ldmatrix.sync.aligned.m8n8.x4.shared.b16 {%0,%1,%2,%3}, [%4];"
                 : "=r"(r0), "=r"(r1), "=r"(r2), "=r"(r3) : "r"(addr));
}

// ---------------- preprocessing kernels ----------------
__global__ void k_init(const void* ei, int E, long long N, int n) {
    int i = blockIdx.x * blockDim.x + threadIdx.x;
    if (i < n) { g_count[i] = 0; g_fill[i] = 0; }
    if (i == 0) {
        const long long* p = (const long long*)ei;
        int is32 = 0;
        for (int j = 0; j < 64 && j < E; j++) {
            long long v = p[j];
            if (v < 0 || v >= N) { is32 = 1; break; }
        }
        g_is32 = is32;
    }
}

__global__ void k_hist(const void* __restrict__ ei, int E) {
    int e = blockIdx.x * blockDim.x + threadIdx.x;
    if (e >= E) return;
    int is32 = g_is32;
    int d = edge_val(ei, is32, (long long)E + e);
    atomicAdd(&g_count[d], 1);
}

// scan over counts; also computes dinv (fused)
__global__ void k_scan1(int n) {
    __shared__ int s[1024];
    int t = threadIdx.x;
    int i = blockIdx.x * 1024 + t;
    int v = (i < n) ? g_count[i] : 0;
    if (i < n) g_dinv[i] = rsqrtf((float)v + 1.0f);
    s[t] = v;
    __syncthreads();
    #pragma unroll
    for (int off = 1; off < 1024; off <<= 1) {
        int x = (t >= off) ? s[t - off] : 0;
        __syncthreads();
        s[t] += x;
        __syncthreads();
    }
    if (i < n) g_rowptr[i] = s[t] - v;
    if (t == 1023) g_bsums[blockIdx.x] = s[1023];
}

__global__ void k_scan2(int nb, int n) {
    if (threadIdx.x == 0 && blockIdx.x == 0) {
        int acc = 0;
        for (int b = 0; b < nb; b++) { int t = g_bsums[b]; g_bsums[b] = acc; acc += t; }
        g_rowptr[n] = acc;
    }
}

__global__ void k_scan3(int n) {
    int i = blockIdx.x * blockDim.x + threadIdx.x;
    if (i < n) g_rowptr[i] += g_bsums[i >> 10];
}

__global__ void k_scatter(const void* __restrict__ ei, int E) {
    int e = blockIdx.x * blockDim.x + threadIdx.x;
    if (e >= E) return;
    int is32 = g_is32;
    int s = edge_val(ei, is32, e);
    int d = edge_val(ei, is32, (long long)E + e);
    int pos = g_rowptr[d] + atomicAdd(&g_fill[d], 1);
    g_esrc[pos]  = s;
    g_enorm[pos] = g_dinv[s] * g_dinv[d];
}

// ---------------- all weight transposes (tf32-rounded) in one kernel ----------
__global__ void k_wtrans_all(const float* __restrict__ W1, const float* __restrict__ W2,
                             const float* __restrict__ W3, const float* __restrict__ W4,
                             const float* __restrict__ W5) {
    int idx = blockIdx.x * 256 + threadIdx.x;
    if (idx < 49152) {                       // wt1: [128][384] from W1[384][128]
        int n = idx / 384, k = idx % 384;
        g_wt1[idx] = round_tf32(W1[(size_t)k * 128 + n]);
    } else if (idx < 49152 + 16384) {        // wt2
        int j = idx - 49152; int n = j / 128, k = j % 128;
        g_wt2[j] = round_tf32(W2[(size_t)k * 128 + n]);
    } else if (idx < 49152 + 32768) {        // wt3
        int j = idx - 49152 - 16384; int n = j / 128, k = j % 128;
        g_wt3[j] = round_tf32(W3[(size_t)k * 128 + n]);
    } else if (idx < 49152 + 49152) {        // wt4
        int j = idx - 49152 - 32768; int n = j / 128, k = j % 128;
        g_wt4[j] = round_tf32(W4[(size_t)k * 128 + n]);
    } else if (idx < 49152 + 49152 + 8192) { // wt5: [64][128] from W5[128][50]
        int j = idx - 49152 - 49152; int n = j / 128, k = j % 128;
        g_wt5[j] = (n < 50) ? round_tf32(W5[(size_t)k * 50 + n]) : 0.f;
    }
}

// ---------------- standalone tf32 GEMM (layer 1 only, KT=384) ----------------
// 3-stage cp.async ring + ldmatrix; 256 threads, block 128x128, warps 2x4.
template<int KT, int BN, int SC, bool CVT>
__global__ __launch_bounds__(256, 2) void k_gemm3(const float* __restrict__ A,
                                                  const float* __restrict__ WT,
                                                  float* __restrict__ C, int M) {
    constexpr int BM = 128, BK = 16;
    constexpr int WN = 4;
    constexpr int WTM = 64, MT = 4;
    constexpr int WTN = BN / WN;
    constexpr int NTL = WTN / 8;
    constexpr int LDR = BK + 4;
    constexpr int ACH = 2;
    constexpr int WCH = BN * 4 / 256;
    constexpr int NK  = KT / BK;
    constexpr int AST = BM * LDR;
    constexpr int WST = BN * LDR;

    extern __shared__ float smem[];
    float* Abase = smem;
    float* Wbase = smem + 3 * AST;

    const int tid = threadIdx.x;
    const int wid = tid >> 5;
    const int lane = tid & 31;
    const int g = lane >> 2;
    const int t = lane & 3;
    const int warp_m = wid / WN;
    const int warp_n = wid % WN;
    const int row0 = blockIdx.x * BM;

    const uint32_t sA = (uint32_t)__cvta_generic_to_shared(Abase);
    const uint32_t sW = (uint32_t)__cvta_generic_to_shared(Wbase);

    float acc[MT][NTL][4];
    #pragma unroll
    for (int i = 0; i < MT; i++)
        #pragma unroll
        for (int j = 0; j < NTL; j++)
            #pragma unroll
            for (int r = 0; r < 4; r++) acc[i][j][r] = 0.f;

    auto load_tile = [&](int i, int st) {
        const int kb = i * BK;
        #pragma unroll
        for (int j = 0; j < ACH; j++) {
            int idx = tid + j * 256;
            int r = idx >> 2, ch = idx & 3;
            int grow = row0 + r;
            const float* src = A + (size_t)grow * KT + kb + ch * 4;
            uint32_t dst = sA + (uint32_t)((st * AST + r * LDR + ch * 4) * 4);
            cp_async16(dst, src, grow < M ? 16 : 0);
        }
        #pragma unroll
        for (int j = 0; j < WCH; j++) {
            int idx = tid + j * 256;
            int n = idx >> 2, ch = idx & 3;
            const float* src = WT + (size_t)n * KT + kb + ch * 4;
            uint32_t dst = sW + (uint32_t)((st * WST + n * LDR + ch * 4) * 4);
            cp_async16(dst, src, 16);
        }
    };

    load_tile(0, 0); cp_commit();
    load_tile(1, 1); cp_commit();

    for (int i = 0; i < NK; i++) {
        const int st = i % 3;
        cp_wait<1>();
        __syncthreads();

        #pragma unroll
        for (int ks = 0; ks < 2; ks++) {
            const int k8 = ks * 8;
            uint32_t bf[NTL][2];
            #pragma unroll
            for (int np = 0; np < NTL / 2; np++) {
                int n0 = warp_n * WTN + np * 16;
                uint32_t ad = sW + (uint32_t)(((st * WST) +
                              (n0 + (lane & 7) + ((lane >> 4) & 1) * 8) * LDR +
                              k8 + ((lane >> 3) & 1) * 4) * 4);
                ldsm_x4(bf[2 * np][0], bf[2 * np][1], bf[2 * np + 1][0], bf[2 * np + 1][1], ad);
            }
            #pragma unroll
            for (int mt = 0; mt < MT; mt++) {
                int mb = warp_m * WTM + mt * 16;
                uint32_t ad = sA + (uint32_t)(((st * AST) +
                              (mb + (lane & 15)) * LDR + k8 + (lane >> 4) * 4) * 4);
                uint32_t a0, a1, a2, a3;
                ldsm_x4(a0, a1, a2, a3, ad);
                if (CVT) {
                    a0 = to_tf32(__uint_as_float(a0));
                    a1 = to_tf32(__uint_as_float(a1));
                    a2 = to_tf32(__uint_as_float(a2));
                    a3 = to_tf32(__uint_as_float(a3));
                }
                #pragma unroll
                for (int nt = 0; nt < NTL; nt++) {
                    asm volatile(
                        "mma.sync.aligned.m16n8k8.row.col.f32.tf32.tf32.f32 "
                        "{%0,%1,%2,%3}, {%4,%5,%6,%7}, {%8,%9}, {%0,%1,%2,%3};"
                        : "+f"(acc[mt][nt][0]), "+f"(acc[mt][nt][1]),
                          "+f"(acc[mt][nt][2]), "+f"(acc[mt][nt][3])
                        : "r"(a0), "r"(a1), "r"(a2), "r"(a3),
                          "r"(bf[nt][0]), "r"(bf[nt][1]));
                }
            }
        }

        if (i + 2 < NK) load_tile(i + 2, (i + 2) % 3);
        cp_commit();
    }

    #pragma unroll
    for (int mt = 0; mt < MT; mt++) {
        int rbase = row0 + warp_m * WTM + mt * 16 + g;
        #pragma unroll
        for (int nt = 0; nt < NTL; nt++) {
            int col = warp_n * WTN + nt * 8 + t * 2;
            if (rbase < M)
                *(float2*)(C + (size_t)rbase * SC + col) =
                    make_float2(acc[mt][nt][0], acc[mt][nt][1]);
            if (rbase + 8 < M)
                *(float2*)(C + (size_t)(rbase + 8) * SC + col) =
                    make_float2(acc[mt][nt][2], acc[mt][nt][3]);
        }
    }
}

// ---------------- fused aggregation + next-layer GEMM ------------------------
// Phase 1: aggregate 128 nodes (relu + bias + tf32 round) into smem A[128][132].
// Phase 2: tensor-core GEMM: hout[block rows] = A @ WT^T  (WT [BN][128]).
// 512 threads = 16 warps. W (BN x 128) prefetched via cp.async during phase 1.
template<int BN, int SC>
__global__ __launch_bounds__(512, 1) void k_fused(const float* __restrict__ hin,
                                                  const float* __restrict__ bias,
                                                  const float* __restrict__ WT,
                                                  float* __restrict__ hout, int n) {
    constexpr int LDR = 132;               // row stride (floats); 16B-aligned, bank-safe
    constexpr int WTN = BN / 4;            // 32 or 16
    constexpr int NTL = WTN / 8;           // 4 or 2
    extern __shared__ float smem[];
    float* As = smem;                      // [128][LDR]
    float* Ws = smem + 128 * LDR;          // [BN][LDR]

    const int tid = threadIdx.x;
    const int wid = tid >> 5;
    const int lane = tid & 31;
    const int row0 = blockIdx.x * 128;

    const uint32_t sA = (uint32_t)__cvta_generic_to_shared(As);
    const uint32_t sW = (uint32_t)__cvta_generic_to_shared(Ws);

    // ---- W prefetch (completes during agg phase) ----
    for (int j = tid; j < BN * 32; j += 512) {
        int nrow = j >> 5, ch = j & 31;
        cp_async16(sW + (uint32_t)((nrow * LDR + ch * 4) * 4),
                   WT + (size_t)nrow * 128 + ch * 4, 16);
    }
    cp_commit();

    // ---- phase 1: aggregation, 8 nodes per warp ----
    const float4* __restrict__ h4 = (const float4*)hin;
    float4 vb = __ldg((const float4*)bias + lane);
    #pragma unroll 1
    for (int i = 0; i < 8; i++) {
        int r = wid * 8 + i;
        int node = row0 + r;
        if (node >= n) break;
        int e = g_rowptr[node];
        const int e1 = g_rowptr[node + 1];

        float4 acc = make_float4(0.f, 0.f, 0.f, 0.f);
        for (; e + 8 <= e1; e += 8) {
            int   s[8]; float w[8]; float4 v[8];
            #pragma unroll
            for (int j = 0; j < 8; j++) { s[j] = g_esrc[e + j]; w[j] = g_enorm[e + j]; }
            #pragma unroll
            for (int j = 0; j < 8; j++) v[j] = __ldg(h4 + s[j] * 32 + lane);
            #pragma unroll
            for (int j = 0; j < 8; j++) {
                acc.x += w[j] * v[j].x; acc.y += w[j] * v[j].y;
                acc.z += w[j] * v[j].z; acc.w += w[j] * v[j].w;
            }
        }
        for (; e < e1; e++) {
            int s0 = g_esrc[e];
            float n0 = g_enorm[e];
            float4 v0 = __ldg(h4 + s0 * 32 + lane);
            acc.x += n0 * v0.x; acc.y += n0 * v0.y; acc.z += n0 * v0.z; acc.w += n0 * v0.w;
        }

        float di = g_dinv[node];
        float sl = di * di;
        float4 vi = __ldg(h4 + node * 32 + lane);
        acc.x = round_tf32(fmaxf(acc.x + sl * vi.x + vb.x, 0.f));
        acc.y = round_tf32(fmaxf(acc.y + sl * vi.y + vb.y, 0.f));
        acc.z = round_tf32(fmaxf(acc.z + sl * vi.z + vb.z, 0.f));
        acc.w = round_tf32(fmaxf(acc.w + sl * vi.w + vb.w, 0.f));
        *(float4*)(As + r * LDR + lane * 4) = acc;
    }

    cp_wait<0>();
    __syncthreads();

    // ---- phase 2: GEMM out of smem ----
    const int g = lane >> 2;
    const int t = lane & 3;
    const int warp_m = wid >> 2;          // 0..3, 32 rows each
    const int warp_n = wid & 3;

    float acc[2][NTL][4];
    #pragma unroll
    for (int i = 0; i < 2; i++)
        #pragma unroll
        for (int j = 0; j < NTL; j++)
            #pragma unroll
            for (int r = 0; r < 4; r++) acc[i][j][r] = 0.f;

    #pragma unroll
    for (int ks = 0; ks < 16; ks++) {
        const int k8 = ks * 8;
        uint32_t bf[NTL][2];
        if (NTL == 4) {
            #pragma unroll
            for (int np = 0; np < 2; np++) {
                int n0 = warp_n * WTN + np * 16;
                uint32_t ad = sW + (uint32_t)(((n0 + (lane & 7) + ((lane >> 4) & 1) * 8) * LDR +
                              k8 + ((lane >> 3) & 1) * 4) * 4);
                ldsm_x4(bf[2 * np][0], bf[2 * np][1], bf[2 * np + 1][0], bf[2 * np + 1][1], ad);
            }
        } else {
            int n0 = warp_n * WTN;
            uint32_t ad = sW + (uint32_t)(((n0 + (lane & 7) + ((lane >> 4) & 1) * 8) * LDR +
                          k8 + ((lane >> 3) & 1) * 4) * 4);
            ldsm_x4(bf[0][0], bf[0][1], bf[1][0], bf[1][1], ad);
        }
        #pragma unroll
        for (int mt = 0; mt < 2; mt++) {
            int mb = warp_m * 32 + mt * 16;
            uint32_t ad = sA + (uint32_t)(((mb + (lane & 15)) * LDR + k8 + (lane >> 4) * 4) * 4);
            uint32_t a0, a1, a2, a3;
            ldsm_x4(a0, a1, a2, a3, ad);
            #pragma unroll
            for (int nt = 0; nt < NTL; nt++) {
                asm volatile(
                    "mma.sync.aligned.m16n8k8.row.col.f32.tf32.tf32.f32 "
                    "{%0,%1,%2,%3}, {%4,%5,%6,%7}, {%8,%9}, {%0,%1,%2,%3};"
                    : "+f"(acc[mt][nt][0]), "+f"(acc[mt][nt][1]),
                      "+f"(acc[mt][nt][2]), "+f"(acc[mt][nt][3])
                    : "r"(a0), "r"(a1), "r"(a2), "r"(a3),
                      "r"(bf[nt][0]), "r"(bf[nt][1]));
            }
        }
    }

    #pragma unroll
    for (int mt = 0; mt < 2; mt++) {
        int rbase = row0 + warp_m * 32 + mt * 16 + g;
        #pragma unroll
        for (int nt = 0; nt < NTL; nt++) {
            int col = warp_n * WTN + nt * 8 + t * 2;
            if (rbase < n)
                *(float2*)(hout + (size_t)rbase * SC + col) =
                    make_float2(acc[mt][nt][0], acc[mt][nt][1]);
            if (rbase + 8 < n)
                *(float2*)(hout + (size_t)(rbase + 8) * SC + col) =
                    make_float2(acc[mt][nt][2], acc[mt][nt][3]);
        }
    }
}

// ---------------- final aggregation (C=50, no relu) --------------------------
template<int NF, int C, int SH, int SO>
__global__ __launch_bounds__(256) void k_agg(const float* __restrict__ h,
                                             const float* __restrict__ b,
                                             float* __restrict__ out, int n) {
    int warp = (blockIdx.x * blockDim.x + threadIdx.x) >> 5;
    int lane = threadIdx.x & 31;
    if (warp >= n) return;
    const int i = warp;
    int e = g_rowptr[i];
    const int e1 = g_rowptr[i + 1];

    float acc[NF];
    #pragma unroll
    for (int j = 0; j < NF; j++) acc[j] = 0.f;

    for (; e + 4 <= e1; e += 4) {
        int s0 = g_esrc[e], s1 = g_esrc[e + 1], s2 = g_esrc[e + 2], s3 = g_esrc[e + 3];
        float n0 = g_enorm[e], n1 = g_enorm[e + 1], n2 = g_enorm[e + 2], n3 = g_enorm[e + 3];
        const float* h0 = h + (size_t)s0 * SH;
        const float* h1 = h + (size_t)s1 * SH;
        const float* h2 = h + (size_t)s2 * SH;
        const float* h3 = h + (size_t)s3 * SH;
        #pragma unroll
        for (int j = 0; j < NF; j++) {
            int f = lane + j * 32;
            if (f < C) {
                acc[j] += n0 * __ldg(h0 + f);
                acc[j] += n1 * __ldg(h1 + f);
                acc[j] += n2 * __ldg(h2 + f);
                acc[j] += n3 * __ldg(h3 + f);
            }
        }
    }
    for (; e < e1; e++) {
        int s0 = g_esrc[e];
        float n0 = g_enorm[e];
        const float* h0 = h + (size_t)s0 * SH;
        #pragma unroll
        for (int j = 0; j < NF; j++) {
            int f = lane + j * 32;
            if (f < C) acc[j] += n0 * __ldg(h0 + f);
        }
    }

    float di = g_dinv[i];
    float sl = di * di;
    const float* hi = h + (size_t)i * SH;
    #pragma unroll
    for (int j = 0; j < NF; j++) {
        int f = lane + j * 32;
        if (f < C)
            out[(size_t)i * SO + f] = acc[j] + sl * __ldg(hi + f) + __ldg(b + f);
    }
}

// ---------------- launch ----------------
extern "C" void kernel_launch(void* const* d_in, const int* in_sizes, int n_in,
                              void* d_out, int out_size) {
    const float* x  = (const float*)d_in[0];
    const void*  ei = d_in[1];
    const float* W1 = (const float*)d_in[2];  const float* b1 = (const float*)d_in[3];
    const float* W2 = (const float*)d_in[4];  const float* b2 = (const float*)d_in[5];
    const float* W3 = (const float*)d_in[6];  const float* b3 = (const float*)d_in[7];
    const float* W4 = (const float*)d_in[8];  const float* b4 = (const float*)d_in[9];
    const float* W5 = (const float*)d_in[10]; const float* b5 = (const float*)d_in[11];

    const int N = in_sizes[0] / 384;
    const int E = in_sizes[1] / 2;

    float *h, *y, *wt1, *wt2, *wt3, *wt4, *wt5;
    cudaGetSymbolAddress((void**)&h, g_h);
    cudaGetSymbolAddress((void**)&y, g_y);
    cudaGetSymbolAddress((void**)&wt1, g_wt1);
    cudaGetSymbolAddress((void**)&wt2, g_wt2);
    cudaGetSymbolAddress((void**)&wt3, g_wt3);
    cudaGetSymbolAddress((void**)&wt4, g_wt4);
    cudaGetSymbolAddress((void**)&wt5, g_wt5);

    const int T = 256;
    const int gN = (N + T - 1) / T;
    const int gE = (E + T - 1) / T;
    const int nb = (N + 1023) / 1024;
    const int gm = (N + 127) / 128;
    const int ga = (N + 7) / 8;

    const int smemG1 = 3 * (128 + 128) * 20 * 4;                 // 61440
    const int smemF128 = (128 + 128) * 132 * 4;                  // 135168
    const int smemF64  = (128 + 64) * 132 * 4;                   // 101376
    cudaFuncSetAttribute(k_gemm3<384, 128, 128, true>,
                         cudaFuncAttributeMaxDynamicSharedMemorySize, smemG1);
    cudaFuncSetAttribute(k_fused<128, 128>,
                         cudaFuncAttributeMaxDynamicSharedMemorySize, smemF128);
    cudaFuncSetAttribute(k_fused<64, 64>,
                         cudaFuncAttributeMaxDynamicSharedMemorySize, smemF64);

    // launch order keeps GEMM1 at launch index 3 (ncu capture slot)
    k_init<<<gN, T>>>(ei, E, (long long)N, N);
    k_wtrans_all<<<(106496 + 255) / 256, T>>>(W1, W2, W3, W4, W5);
    k_hist<<<gE, T>>>(ei, E);
    k_gemm3<384, 128, 128, true><<<gm, T, smemG1>>>(x, wt1, h, N);   // GEMM1
    k_scan1<<<nb, 1024>>>(N);
    k_scan2<<<1, 32>>>(nb, N);
    k_scan3<<<gN, T>>>(N);
    k_scatter<<<gE, T>>>(ei, E);

    // fused agg_l + GEMM_{l+1}
    k_fused<128, 128><<<gm, 512, smemF128>>>(h, b1, wt2, y, N);
    k_fused<128, 128><<<gm, 512, smemF128>>>(y, b2, wt3, h, N);
    k_fused<128, 128><<<gm, 512, smemF128>>>(h, b3, wt4, y, N);
    k_fused<64, 64><<<gm, 512, smemF64>>>(y, b4, wt5, h, N);
    // final aggregation (layer 5): h (stride 64) -> d_out (stride 50)
    k_agg<2, 50, 64, 50><<<ga, T>>>(h, b5, (float*)d_out, N);
}

// round 7
// speedup vs baseline: 1.5074x; 1.5074x over previous
#include <cuda_runtime.h>
#include <cuda_fp16.h>
#include <cstdint>

#define N_NODES_MAX 100000
#define N_EDGES_MAX 1600000

// ---------------- device scratch (no allocations allowed) ----------------
__device__ __half g_h[(size_t)N_NODES_MAX * 128];   // GEMM output (fp16, gathered)
__device__ float  g_y[(size_t)N_NODES_MAX * 128];   // agg output (fp32/tf32, GEMM A)
__device__ float g_dinv[N_NODES_MAX];
__device__ int   g_count[N_NODES_MAX];
__device__ int   g_fill[N_NODES_MAX];
__device__ int   g_rowptr[N_NODES_MAX + 1];
__device__ int   g_esrc[N_EDGES_MAX];
__device__ float g_enorm[N_EDGES_MAX];
__device__ int   g_bsums[256];
__device__ int   g_is32;
// transposed tf32-rounded weights: WT[n][k]
__device__ float g_wt1[128 * 384];
__device__ float g_wt2[128 * 128];
__device__ float g_wt3[128 * 128];
__device__ float g_wt4[128 * 128];
__device__ float g_wt5[64 * 128];

// ---------------- helpers ----------------
__device__ __forceinline__ int edge_val(const void* ei, int is32, long long idx) {
    if (is32) return ((const int*)ei)[idx];
    return (int)((const long long*)ei)[idx];
}
__device__ __forceinline__ uint32_t to_tf32(float f) {
    uint32_t r;
    asm("cvt.rna.tf32.f32 %0, %1;" : "=r"(r) : "f"(f));
    return r;
}
__device__ __forceinline__ float round_tf32(float f) {
    return __uint_as_float(to_tf32(f));
}
__device__ __forceinline__ void cp_async16(uint32_t dst, const void* src, int srcsize) {
    asm volatile("cp.async.ca.shared.global [%0], [%1], 16, %2;"
                 :: "r"(dst), "l"(src), "r"(srcsize));
}
__device__ __forceinline__ void cp_commit() { asm volatile("cp.async.commit_group;"); }
template<int N>
__device__ __forceinline__ void cp_wait() { asm volatile("cp.async.wait_group %0;" :: "n"(N)); }

__device__ __forceinline__ void ldsm_x4(uint32_t& r0, uint32_t& r1, uint32_t& r2, uint32_t& r3,
                                        uint32_t addr) {
    asm volatile("ldmatrix.sync.aligned.m8n8.x4.shared.b16 {%0,%1,%2,%3}, [%4];"
                 : "=r"(r0), "=r"(r1), "=r"(r2), "=r"(r3) : "r"(addr));
}

// ---------------- preprocessing kernels ----------------
__global__ void k_init(const void* ei, int E, long long N, int n) {
    int i = blockIdx.x * blockDim.x + threadIdx.x;
    if (i < n) { g_count[i] = 0; g_fill[i] = 0; }
    if (i == 0) {
        const long long* p = (const long long*)ei;
        int is32 = 0;
        for (int j = 0; j < 64 && j < E; j++) {
            long long v = p[j];
            if (v < 0 || v >= N) { is32 = 1; break; }
        }
        g_is32 = is32;
    }
}

__global__ void k_hist(const void* __restrict__ ei, int E) {
    int e = blockIdx.x * blockDim.x + threadIdx.x;
    if (e >= E) return;
    int is32 = g_is32;
    int d = edge_val(ei, is32, (long long)E + e);
    atomicAdd(&g_count[d], 1);
}

// scan over counts; also computes dinv (fused)
__global__ void k_scan1(int n) {
    __shared__ int s[1024];
    int t = threadIdx.x;
    int i = blockIdx.x * 1024 + t;
    int v = (i < n) ? g_count[i] : 0;
    if (i < n) g_dinv[i] = rsqrtf((float)v + 1.0f);
    s[t] = v;
    __syncthreads();
    #pragma unroll
    for (int off = 1; off < 1024; off <<= 1) {
        int x = (t >= off) ? s[t - off] : 0;
        __syncthreads();
        s[t] += x;
        __syncthreads();
    }
    if (i < n) g_rowptr[i] = s[t] - v;
    if (t == 1023) g_bsums[blockIdx.x] = s[1023];
}

__global__ void k_scan2(int nb, int n) {
    if (threadIdx.x == 0 && blockIdx.x == 0) {
        int acc = 0;
        for (int b = 0; b < nb; b++) { int t = g_bsums[b]; g_bsums[b] = acc; acc += t; }
        g_rowptr[n] = acc;
    }
}

__global__ void k_scan3(int n) {
    int i = blockIdx.x * blockDim.x + threadIdx.x;
    if (i < n) g_rowptr[i] += g_bsums[i >> 10];
}

__global__ void k_scatter(const void* __restrict__ ei, int E) {
    int e = blockIdx.x * blockDim.x + threadIdx.x;
    if (e >= E) return;
    int is32 = g_is32;
    int s = edge_val(ei, is32, e);
    int d = edge_val(ei, is32, (long long)E + e);
    int pos = g_rowptr[d] + atomicAdd(&g_fill[d], 1);
    g_esrc[pos]  = s;
    g_enorm[pos] = g_dinv[s] * g_dinv[d];
}

// ---------------- all weight transposes (tf32-rounded) in one kernel ----------
__global__ void k_wtrans_all(const float* __restrict__ W1, const float* __restrict__ W2,
                             const float* __restrict__ W3, const float* __restrict__ W4,
                             const float* __restrict__ W5) {
    int idx = blockIdx.x * 256 + threadIdx.x;
    if (idx < 49152) {                       // wt1: [128][384] from W1[384][128]
        int n = idx / 384, k = idx % 384;
        g_wt1[idx] = round_tf32(W1[(size_t)k * 128 + n]);
    } else if (idx < 49152 + 16384) {        // wt2
        int j = idx - 49152; int n = j / 128, k = j % 128;
        g_wt2[j] = round_tf32(W2[(size_t)k * 128 + n]);
    } else if (idx < 49152 + 32768) {        // wt3
        int j = idx - 49152 - 16384; int n = j / 128, k = j % 128;
        g_wt3[j] = round_tf32(W3[(size_t)k * 128 + n]);
    } else if (idx < 49152 + 49152) {        // wt4
        int j = idx - 49152 - 32768; int n = j / 128, k = j % 128;
        g_wt4[j] = round_tf32(W4[(size_t)k * 128 + n]);
    } else if (idx < 49152 + 49152 + 8192) { // wt5: [64][128] from W5[128][50]
        int j = idx - 49152 - 49152; int n = j / 128, k = j % 128;
        g_wt5[j] = (n < 50) ? round_tf32(W5[(size_t)k * 50 + n]) : 0.f;
    }
}

// ---------------- tf32 tensor-core GEMM (3-stage cp.async + ldmatrix) --------
// C[M, SC] = A[M, KT] @ WT^T  (WT is [BN][KT], tf32-rounded, n-major)
// Output written as fp16 (half2 stores). 256 threads, block 128xBN, warps 2x4.
template<int KT, int BN, int SC, bool CVT>
__global__ __launch_bounds__(256, 2) void k_gemm3(const float* __restrict__ A,
                                                  const float* __restrict__ WT,
                                                  __half* __restrict__ C, int M) {
    constexpr int BM = 128, BK = 16;
    constexpr int WN = 4;
    constexpr int WTM = 64, MT = 4;
    constexpr int WTN = BN / WN;
    constexpr int NTL = WTN / 8;
    constexpr int LDR = BK + 4;
    constexpr int ACH = 2;
    constexpr int WCH = BN * 4 / 256;
    constexpr int NK  = KT / BK;
    constexpr int AST = BM * LDR;
    constexpr int WST = BN * LDR;

    extern __shared__ float smem[];
    float* Abase = smem;
    float* Wbase = smem + 3 * AST;

    const int tid = threadIdx.x;
    const int wid = tid >> 5;
    const int lane = tid & 31;
    const int g = lane >> 2;
    const int t = lane & 3;
    const int warp_m = wid / WN;
    const int warp_n = wid % WN;
    const int row0 = blockIdx.x * BM;

    const uint32_t sA = (uint32_t)__cvta_generic_to_shared(Abase);
    const uint32_t sW = (uint32_t)__cvta_generic_to_shared(Wbase);

    float acc[MT][NTL][4];
    #pragma unroll
    for (int i = 0; i < MT; i++)
        #pragma unroll
        for (int j = 0; j < NTL; j++)
            #pragma unroll
            for (int r = 0; r < 4; r++) acc[i][j][r] = 0.f;

    auto load_tile = [&](int i, int st) {
        const int kb = i * BK;
        #pragma unroll
        for (int j = 0; j < ACH; j++) {
            int idx = tid + j * 256;
            int r = idx >> 2, ch = idx & 3;
            int grow = row0 + r;
            const float* src = A + (size_t)grow * KT + kb + ch * 4;
            uint32_t dst = sA + (uint32_t)((st * AST + r * LDR + ch * 4) * 4);
            cp_async16(dst, src, grow < M ? 16 : 0);
        }
        #pragma unroll
        for (int j = 0; j < WCH; j++) {
            int idx = tid + j * 256;
            int n = idx >> 2, ch = idx & 3;
            const float* src = WT + (size_t)n * KT + kb + ch * 4;
            uint32_t dst = sW + (uint32_t)((st * WST + n * LDR + ch * 4) * 4);
            cp_async16(dst, src, 16);
        }
    };

    load_tile(0, 0); cp_commit();
    load_tile(1, 1); cp_commit();

    for (int i = 0; i < NK; i++) {
        const int st = i % 3;
        cp_wait<1>();
        __syncthreads();

        #pragma unroll
        for (int ks = 0; ks < 2; ks++) {
            const int k8 = ks * 8;
            uint32_t bf[NTL][2];
            #pragma unroll
            for (int np = 0; np < NTL / 2; np++) {
                int n0 = warp_n * WTN + np * 16;
                uint32_t ad = sW + (uint32_t)(((st * WST) +
                              (n0 + (lane & 7) + ((lane >> 4) & 1) * 8) * LDR +
                              k8 + ((lane >> 3) & 1) * 4) * 4);
                ldsm_x4(bf[2 * np][0], bf[2 * np][1], bf[2 * np + 1][0], bf[2 * np + 1][1], ad);
            }
            #pragma unroll
            for (int mt = 0; mt < MT; mt++) {
                int mb = warp_m * WTM + mt * 16;
                uint32_t ad = sA + (uint32_t)(((st * AST) +
                              (mb + (lane & 15)) * LDR + k8 + (lane >> 4) * 4) * 4);
                uint32_t a0, a1, a2, a3;
                ldsm_x4(a0, a1, a2, a3, ad);
                if (CVT) {
                    a0 = to_tf32(__uint_as_float(a0));
                    a1 = to_tf32(__uint_as_float(a1));
                    a2 = to_tf32(__uint_as_float(a2));
                    a3 = to_tf32(__uint_as_float(a3));
                }
                #pragma unroll
                for (int nt = 0; nt < NTL; nt++) {
                    asm volatile(
                        "mma.sync.aligned.m16n8k8.row.col.f32.tf32.tf32.f32 "
                        "{%0,%1,%2,%3}, {%4,%5,%6,%7}, {%8,%9}, {%0,%1,%2,%3};"
                        : "+f"(acc[mt][nt][0]), "+f"(acc[mt][nt][1]),
                          "+f"(acc[mt][nt][2]), "+f"(acc[mt][nt][3])
                        : "r"(a0), "r"(a1), "r"(a2), "r"(a3),
                          "r"(bf[nt][0]), "r"(bf[nt][1]));
                }
            }
        }

        if (i + 2 < NK) load_tile(i + 2, (i + 2) % 3);
        cp_commit();
    }

    // ---- store C as fp16 ----
    #pragma unroll
    for (int mt = 0; mt < MT; mt++) {
        int rbase = row0 + warp_m * WTM + mt * 16 + g;
        #pragma unroll
        for (int nt = 0; nt < NTL; nt++) {
            int col = warp_n * WTN + nt * 8 + t * 2;
            if (rbase < M)
                *(__half2*)(C + (size_t)rbase * SC + col) =
                    __floats2half2_rn(acc[mt][nt][0], acc[mt][nt][1]);
            if (rbase + 8 < M)
                *(__half2*)(C + (size_t)(rbase + 8) * SC + col) =
                    __floats2half2_rn(acc[mt][nt][2], acc[mt][nt][3]);
        }
    }
}

// ---------------- aggregation (C=128): warp per node, half gathers ----------
// Gathers fp16 h rows (256B), accumulates fp32, writes tf32-rounded fp32 y.
__global__ __launch_bounds__(256) void k_agg128(const __half* __restrict__ hin,
                                                const float* __restrict__ b,
                                                float* __restrict__ out, int n) {
    int warp = (blockIdx.x * blockDim.x + threadIdx.x) >> 5;
    int lane = threadIdx.x & 31;
    if (warp >= n) return;
    const uint2* __restrict__ h2 = (const uint2*)hin;   // 4 halves per uint2; 32/row
    int e = g_rowptr[warp];
    const int e1 = g_rowptr[warp + 1];

    float4 acc = make_float4(0.f, 0.f, 0.f, 0.f);

    for (; e + 8 <= e1; e += 8) {
        int   s[8]; float w[8]; uint2 v[8];
        #pragma unroll
        for (int j = 0; j < 8; j++) { s[j] = g_esrc[e + j]; w[j] = g_enorm[e + j]; }
        #pragma unroll
        for (int j = 0; j < 8; j++) v[j] = __ldg(h2 + s[j] * 32 + lane);
        #pragma unroll
        for (int j = 0; j < 8; j++) {
            float2 f0 = __half22float2(*(__half2*)&v[j].x);
            float2 f1 = __half22float2(*(__half2*)&v[j].y);
            acc.x += w[j] * f0.x; acc.y += w[j] * f0.y;
            acc.z += w[j] * f1.x; acc.w += w[j] * f1.y;
        }
    }
    for (; e < e1; e++) {
        int s0 = g_esrc[e];
        float n0 = g_enorm[e];
        uint2 v0 = __ldg(h2 + s0 * 32 + lane);
        float2 f0 = __half22float2(*(__half2*)&v0.x);
        float2 f1 = __half22float2(*(__half2*)&v0.y);
        acc.x += n0 * f0.x; acc.y += n0 * f0.y;
        acc.z += n0 * f1.x; acc.w += n0 * f1.y;
    }

    float di = g_dinv[warp];
    float sl = di * di;
    uint2 vr = __ldg(h2 + warp * 32 + lane);
    float2 vi0 = __half22float2(*(__half2*)&vr.x);
    float2 vi1 = __half22float2(*(__half2*)&vr.y);
    float4 vb = __ldg((const float4*)b + lane);
    acc.x = round_tf32(fmaxf(acc.x + sl * vi0.x + vb.x, 0.f));
    acc.y = round_tf32(fmaxf(acc.y + sl * vi0.y + vb.y, 0.f));
    acc.z = round_tf32(fmaxf(acc.z + sl * vi1.x + vb.z, 0.f));
    acc.w = round_tf32(fmaxf(acc.w + sl * vi1.y + vb.w, 0.f));
    ((float4*)out)[warp * 32 + lane] = acc;
}

// ---------------- final aggregation (C=50, half input, no relu) --------------
__global__ __launch_bounds__(256) void k_agg_fin(const __half* __restrict__ h,
                                                 const float* __restrict__ b,
                                                 float* __restrict__ out, int n) {
    int warp = (blockIdx.x * blockDim.x + threadIdx.x) >> 5;
    int lane = threadIdx.x & 31;
    if (warp >= n) return;
    const int i = warp;
    int e = g_rowptr[i];
    const int e1 = g_rowptr[i + 1];
    const int f0 = lane;            // < 32
    const int f1 = lane + 32;       // < 50 for lanes 0..17

    float a0 = 0.f, a1 = 0.f;
    for (; e + 4 <= e1; e += 4) {
        int s0 = g_esrc[e], s1 = g_esrc[e + 1], s2 = g_esrc[e + 2], s3 = g_esrc[e + 3];
        float n0 = g_enorm[e], n1 = g_enorm[e + 1], n2 = g_enorm[e + 2], n3 = g_enorm[e + 3];
        const __half* p0 = h + (size_t)s0 * 64;
        const __half* p1 = h + (size_t)s1 * 64;
        const __half* p2 = h + (size_t)s2 * 64;
        const __half* p3 = h + (size_t)s3 * 64;
        a0 += n0 * __half2float(__ldg(p0 + f0));
        a0 += n1 * __half2float(__ldg(p1 + f0));
        a0 += n2 * __half2float(__ldg(p2 + f0));
        a0 += n3 * __half2float(__ldg(p3 + f0));
        if (f1 < 50) {
            a1 += n0 * __half2float(__ldg(p0 + f1));
            a1 += n1 * __half2float(__ldg(p1 + f1));
            a1 += n2 * __half2float(__ldg(p2 + f1));
            a1 += n3 * __half2float(__ldg(p3 + f1));
        }
    }
    for (; e < e1; e++) {
        int s0 = g_esrc[e];
        float n0 = g_enorm[e];
        const __half* p0 = h + (size_t)s0 * 64;
        a0 += n0 * __half2float(__ldg(p0 + f0));
        if (f1 < 50) a1 += n0 * __half2float(__ldg(p0 + f1));
    }

    float di = g_dinv[i];
    float sl = di * di;
    const __half* hi = h + (size_t)i * 64;
    out[(size_t)i * 50 + f0] = a0 + sl * __half2float(__ldg(hi + f0)) + __ldg(b + f0);
    if (f1 < 50)
        out[(size_t)i * 50 + f1] = a1 + sl * __half2float(__ldg(hi + f1)) + __ldg(b + f1);
}

// ---------------- launch ----------------
extern "C" void kernel_launch(void* const* d_in, const int* in_sizes, int n_in,
                              void* d_out, int out_size) {
    const float* x  = (const float*)d_in[0];
    const void*  ei = d_in[1];
    const float* W1 = (const float*)d_in[2];  const float* b1 = (const float*)d_in[3];
    const float* W2 = (const float*)d_in[4];  const float* b2 = (const float*)d_in[5];
    const float* W3 = (const float*)d_in[6];  const float* b3 = (const float*)d_in[7];
    const float* W4 = (const float*)d_in[8];  const float* b4 = (const float*)d_in[9];
    const float* W5 = (const float*)d_in[10]; const float* b5 = (const float*)d_in[11];

    const int N = in_sizes[0] / 384;
    const int E = in_sizes[1] / 2;

    __half* h;
    float *y, *wt1, *wt2, *wt3, *wt4, *wt5;
    cudaGetSymbolAddress((void**)&h, g_h);
    cudaGetSymbolAddress((void**)&y, g_y);
    cudaGetSymbolAddress((void**)&wt1, g_wt1);
    cudaGetSymbolAddress((void**)&wt2, g_wt2);
    cudaGetSymbolAddress((void**)&wt3, g_wt3);
    cudaGetSymbolAddress((void**)&wt4, g_wt4);
    cudaGetSymbolAddress((void**)&wt5, g_wt5);

    const int T = 256;
    const int gN = (N + T - 1) / T;
    const int gE = (E + T - 1) / T;
    const int nb = (N + 1023) / 1024;
    const int gm = (N + 127) / 128;
    const int ga = (N + 7) / 8;

    const int smem128 = 3 * (128 + 128) * 20 * 4;   // 61440
    const int smem64  = 3 * (128 + 64) * 20 * 4;    // 46080
    cudaFuncSetAttribute(k_gemm3<384, 128, 128, true>,
                         cudaFuncAttributeMaxDynamicSharedMemorySize, smem128);
    cudaFuncSetAttribute(k_gemm3<128, 128, 128, false>,
                         cudaFuncAttributeMaxDynamicSharedMemorySize, smem128);
    cudaFuncSetAttribute(k_gemm3<128, 64, 64, false>,
                         cudaFuncAttributeMaxDynamicSharedMemorySize, smem64);

    // launch order keeps GEMM1 at launch index 3 (ncu capture slot)
    k_init<<<gN, T>>>(ei, E, (long long)N, N);
    k_wtrans_all<<<(106496 + 255) / 256, T>>>(W1, W2, W3, W4, W5);
    k_hist<<<gE, T>>>(ei, E);
    k_gemm3<384, 128, 128, true><<<gm, T, smem128>>>(x, wt1, h, N);   // GEMM1
    k_scan1<<<nb, 1024>>>(N);
    k_scan2<<<1, 32>>>(nb, N);
    k_scan3<<<gN, T>>>(N);
    k_scatter<<<gE, T>>>(ei, E);

    // layer 1 aggregation (half gathers -> tf32-rounded fp32 y)
    k_agg128<<<ga, T>>>(h, b1, y, N);
    // layers 2-4
    k_gemm3<128, 128, 128, false><<<gm, T, smem128>>>(y, wt2, h, N);
    k_agg128<<<ga, T>>>(h, b2, y, N);
    k_gemm3<128, 128, 128, false><<<gm, T, smem128>>>(y, wt3, h, N);
    k_agg128<<<ga, T>>>(h, b3, y, N);
    k_gemm3<128, 128, 128, false><<<gm, T, smem128>>>(y, wt4, h, N);
    k_agg128<<<ga, T>>>(h, b4, y, N);
    // layer 5: 128 -> 50 (64 padded cols, fp16), then final aggregation
    k_gemm3<128, 64, 64, false><<<gm, T, smem64>>>(y, wt5, h, N);
    k_agg_fin<<<ga, T>>>(h, b5, (float*)d_out, N);
}

// round 9
// speedup vs baseline: 1.6962x; 1.1252x over previous
#include <cuda_runtime.h>
#include <cuda_fp16.h>
#include <cstdint>

#define N_NODES_MAX 100000
#define N_EDGES_MAX 1600000

// ---------------- device scratch (no allocations allowed) ----------------
__device__ __half g_h[(size_t)N_NODES_MAX * 128];   // GEMM output (fp16, gathered)
__device__ __half g_y[(size_t)N_NODES_MAX * 128];   // agg output (fp16, GEMM A)
__device__ __half g_x16[(size_t)N_NODES_MAX * 384]; // fp16 copy of input x
__device__ float g_dinv[N_NODES_MAX];
__device__ int   g_count[N_NODES_MAX];
__device__ int   g_fill[N_NODES_MAX];
__device__ int   g_rowptr[N_NODES_MAX + 1];
__device__ int   g_esrc[N_EDGES_MAX];
__device__ float g_enorm[N_EDGES_MAX];
__device__ int   g_bsums[256];
__device__ int   g_is32;
// transposed fp16 weights: WT[n][k]
__device__ __half g_wt1[128 * 384];
__device__ __half g_wt2[128 * 128];
__device__ __half g_wt3[128 * 128];
__device__ __half g_wt4[128 * 128];
__device__ __half g_wt5[64 * 128];

// ---------------- helpers ----------------
__device__ __forceinline__ int edge_val(const void* ei, int is32, long long idx) {
    if (is32) return ((const int*)ei)[idx];
    return (int)((const long long*)ei)[idx];
}
__device__ __forceinline__ void cp_async16(uint32_t dst, const void* src, int srcsize) {
    asm volatile("cp.async.ca.shared.global [%0], [%1], 16, %2;"
                 :: "r"(dst), "l"(src), "r"(srcsize));
}
__device__ __forceinline__ void cp_commit() { asm volatile("cp.async.commit_group;"); }
template<int N>
__device__ __forceinline__ void cp_wait() { asm volatile("cp.async.wait_group %0;" :: "n"(N)); }

__device__ __forceinline__ void ldsm_x4(uint32_t& r0, uint32_t& r1, uint32_t& r2, uint32_t& r3,
                                        uint32_t addr) {
    asm volatile("ldmatrix.sync.aligned.m8n8.x4.shared.b16 {%0,%1,%2,%3}, [%4];"
                 : "=r"(r0), "=r"(r1), "=r"(r2), "=r"(r3) : "r"(addr));
}

// ---------------- preprocessing kernels ----------------
__global__ void k_init(const void* ei, int E, long long N, int n) {
    int i = blockIdx.x * blockDim.x + threadIdx.x;
    if (i < n) { g_count[i] = 0; g_fill[i] = 0; }
    if (i == 0) {
        const long long* p = (const long long*)ei;
        int is32 = 0;
        for (int j = 0; j < 64 && j < E; j++) {
            long long v = p[j];
            if (v < 0 || v >= N) { is32 = 1; break; }
        }
        g_is32 = is32;
    }
}

// convert x (fp32) to fp16
__global__ void k_x16(const float* __restrict__ x, int total4) {
    int i = blockIdx.x * blockDim.x + threadIdx.x;
    if (i >= total4) return;
    float4 v = __ldg((const float4*)x + i);
    __half2 a = __floats2half2_rn(v.x, v.y);
    __half2 b = __floats2half2_rn(v.z, v.w);
    uint2 o;
    o.x = *(uint32_t*)&a;
    o.y = *(uint32_t*)&b;
    ((uint2*)g_x16)[i] = o;
}

__global__ void k_hist(const void* __restrict__ ei, int E) {
    int e = blockIdx.x * blockDim.x + threadIdx.x;
    if (e >= E) return;
    int is32 = g_is32;
    int d = edge_val(ei, is32, (long long)E + e);
    atomicAdd(&g_count[d], 1);
}

// scan over counts; also computes dinv (fused)
__global__ void k_scan1(int n) {
    __shared__ int s[1024];
    int t = threadIdx.x;
    int i = blockIdx.x * 1024 + t;
    int v = (i < n) ? g_count[i] : 0;
    if (i < n) g_dinv[i] = rsqrtf((float)v + 1.0f);
    s[t] = v;
    __syncthreads();
    #pragma unroll
    for (int off = 1; off < 1024; off <<= 1) {
        int x = (t >= off) ? s[t - off] : 0;
        __syncthreads();
        s[t] += x;
        __syncthreads();
    }
    if (i < n) g_rowptr[i] = s[t] - v;
    if (t == 1023) g_bsums[blockIdx.x] = s[1023];
}

__global__ void k_scan2(int nb, int n) {
    if (threadIdx.x == 0 && blockIdx.x == 0) {
        int acc = 0;
        for (int b = 0; b < nb; b++) { int t = g_bsums[b]; g_bsums[b] = acc; acc += t; }
        g_rowptr[n] = acc;
    }
}

__global__ void k_scan3(int n) {
    int i = blockIdx.x * blockDim.x + threadIdx.x;
    if (i < n) g_rowptr[i] += g_bsums[i >> 10];
}

__global__ void k_scatter(const void* __restrict__ ei, int E) {
    int e = blockIdx.x * blockDim.x + threadIdx.x;
    if (e >= E) return;
    int is32 = g_is32;
    int s = edge_val(ei, is32, e);
    int d = edge_val(ei, is32, (long long)E + e);
    int pos = g_rowptr[d] + atomicAdd(&g_fill[d], 1);
    g_esrc[pos]  = s;
    g_enorm[pos] = g_dinv[s] * g_dinv[d];
}

// ---------------- all weight transposes (fp16) in one kernel ----------------
__global__ void k_wtrans_all(const float* __restrict__ W1, const float* __restrict__ W2,
                             const float* __restrict__ W3, const float* __restrict__ W4,
                             const float* __restrict__ W5) {
    int idx = blockIdx.x * 256 + threadIdx.x;
    if (idx < 49152) {                       // wt1: [128][384] from W1[384][128]
        int n = idx / 384, k = idx % 384;
        g_wt1[idx] = __float2half_rn(W1[(size_t)k * 128 + n]);
    } else if (idx < 49152 + 16384) {        // wt2
        int j = idx - 49152; int n = j / 128, k = j % 128;
        g_wt2[j] = __float2half_rn(W2[(size_t)k * 128 + n]);
    } else if (idx < 49152 + 32768) {        // wt3
        int j = idx - 49152 - 16384; int n = j / 128, k = j % 128;
        g_wt3[j] = __float2half_rn(W3[(size_t)k * 128 + n]);
    } else if (idx < 49152 + 49152) {        // wt4
        int j = idx - 49152 - 32768; int n = j / 128, k = j % 128;
        g_wt4[j] = __float2half_rn(W4[(size_t)k * 128 + n]);
    } else if (idx < 49152 + 49152 + 8192) { // wt5: [64][128] from W5[128][50]
        int j = idx - 49152 - 49152; int n = j / 128, k = j % 128;
        g_wt5[j] = (n < 50) ? __float2half_rn(W5[(size_t)k * 50 + n]) : __float2half_rn(0.f);
    }
}

// ---------------- fp16 tensor-core GEMM (3-stage cp.async + ldmatrix) --------
// C[M, SC] = A[M, KT] @ WT^T  (A fp16 row-major, WT fp16 [BN][KT] n-major)
// mma m16n8k16 f16 with fp32 accumulate; output fp16.
// 256 threads = 8 warps; block tile 128 x BN, BK = 32 halves; warps 2 x 4.
template<int KT, int BN, int SC>
__global__ __launch_bounds__(256, 2) void k_gemm16(const __half* __restrict__ A,
                                                   const __half* __restrict__ WT,
                                                   __half* __restrict__ C, int M) {
    constexpr int BM = 128, BKH = 32;       // k-tile in halves
    constexpr int WN = 4;
    constexpr int WTM = 64, MT = 4;
    constexpr int WTN = BN / WN;            // 32 or 16
    constexpr int NTL = WTN / 8;            // 4 or 2
    constexpr int LDR = BKH + 8;            // 40 halves = 80B rows, 16B-aligned pad
    constexpr int ACH = BM * 4 / 256;       // 2 chunks/thread (4×16B per row)
    constexpr int WCH = BN * 4 / 256;       // 2 or 1
    constexpr int NK  = KT / BKH;
    constexpr int AST = BM * LDR;           // halves per A stage
    constexpr int WST = BN * LDR;

    extern __shared__ __half smem[];
    __half* Abase = smem;
    __half* Wbase = smem + 3 * AST;

    const int tid = threadIdx.x;
    const int wid = tid >> 5;
    const int lane = tid & 31;
    const int g = lane >> 2;
    const int t = lane & 3;
    const int warp_m = wid / WN;
    const int warp_n = wid % WN;
    const int row0 = blockIdx.x * BM;

    const uint32_t sA = (uint32_t)__cvta_generic_to_shared(Abase);
    const uint32_t sW = (uint32_t)__cvta_generic_to_shared(Wbase);

    float acc[MT][NTL][4];
    #pragma unroll
    for (int i = 0; i < MT; i++)
        #pragma unroll
        for (int j = 0; j < NTL; j++)
            #pragma unroll
            for (int r = 0; r < 4; r++) acc[i][j][r] = 0.f;

    auto load_tile = [&](int i, int st) {
        const int kb = i * BKH;
        #pragma unroll
        for (int j = 0; j < ACH; j++) {
            int idx = tid + j * 256;
            int r = idx >> 2, ch = idx & 3;       // ch: 4 × 16B (8 halves)
            int grow = row0 + r;
            const __half* src = A + (size_t)grow * KT + kb + ch * 8;
            uint32_t dst = sA + (uint32_t)((st * AST + r * LDR + ch * 8) * 2);
            cp_async16(dst, src, grow < M ? 16 : 0);
        }
        #pragma unroll
        for (int j = 0; j < WCH; j++) {
            int idx = tid + j * 256;
            int n = idx >> 2, ch = idx & 3;
            const __half* src = WT + (size_t)n * KT + kb + ch * 8;
            uint32_t dst = sW + (uint32_t)((st * WST + n * LDR + ch * 8) * 2);
            cp_async16(dst, src, 16);
        }
    };

    load_tile(0, 0); cp_commit();
    load_tile(1, 1); cp_commit();

    for (int i = 0; i < NK; i++) {
        const int st = i % 3;
        cp_wait<1>();
        __syncthreads();

        #pragma unroll
        for (int ks = 0; ks < 2; ks++) {
            const int k16 = ks * 16;              // halves
            uint32_t bf[NTL][2];
            #pragma unroll
            for (int np = 0; np < NTL / 2; np++) {
                int n0 = warp_n * WTN + np * 16;
                // x4 mats: (n0-7,k0-7),(n0-7,k8-15),(n8-15,k0-7),(n8-15,k8-15)
                uint32_t ad = sW + (uint32_t)(((st * WST) +
                              (n0 + (lane & 7) + ((lane >> 4) & 1) * 8) * LDR +
                              k16 + ((lane >> 3) & 1) * 8) * 2);
                ldsm_x4(bf[2 * np][0], bf[2 * np][1], bf[2 * np + 1][0], bf[2 * np + 1][1], ad);
            }
            #pragma unroll
            for (int mt = 0; mt < MT; mt++) {
                int mb = warp_m * WTM + mt * 16;
                // x4 mats: (m0-7,k0-7),(m8-15,k0-7),(m0-7,k8-15),(m8-15,k8-15)
                uint32_t ad = sA + (uint32_t)(((st * AST) +
                              (mb + (lane & 15)) * LDR + k16 + (lane >> 4) * 8) * 2);
                uint32_t a0, a1, a2, a3;
                ldsm_x4(a0, a1, a2, a3, ad);
                #pragma unroll
                for (int nt = 0; nt < NTL; nt++) {
                    asm volatile(
                        "mma.sync.aligned.m16n8k16.row.col.f32.f16.f16.f32 "
                        "{%0,%1,%2,%3}, {%4,%5,%6,%7}, {%8,%9}, {%0,%1,%2,%3};"
                        : "+f"(acc[mt][nt][0]), "+f"(acc[mt][nt][1]),
                          "+f"(acc[mt][nt][2]), "+f"(acc[mt][nt][3])
                        : "r"(a0), "r"(a1), "r"(a2), "r"(a3),
                          "r"(bf[nt][0]), "r"(bf[nt][1]));
                }
            }
        }

        if (i + 2 < NK) load_tile(i + 2, (i + 2) % 3);
        cp_commit();
    }

    // ---- store C as fp16 ----
    #pragma unroll
    for (int mt = 0; mt < MT; mt++) {
        int rbase = row0 + warp_m * WTM + mt * 16 + g;
        #pragma unroll
        for (int nt = 0; nt < NTL; nt++) {
            int col = warp_n * WTN + nt * 8 + t * 2;
            if (rbase < M)
                *(__half2*)(C + (size_t)rbase * SC + col) =
                    __floats2half2_rn(acc[mt][nt][0], acc[mt][nt][1]);
            if (rbase + 8 < M)
                *(__half2*)(C + (size_t)(rbase + 8) * SC + col) =
                    __floats2half2_rn(acc[mt][nt][2], acc[mt][nt][3]);
        }
    }
}

// ---------------- aggregation (C=128): warp per node, half in/half out -------
__global__ __launch_bounds__(256) void k_agg128(const __half* __restrict__ hin,
                                                const float* __restrict__ b,
                                                __half* __restrict__ out, int n) {
    int warp = (blockIdx.x * blockDim.x + threadIdx.x) >> 5;
    int lane = threadIdx.x & 31;
    if (warp >= n) return;
    const uint2* __restrict__ h2 = (const uint2*)hin;   // 4 halves per uint2; 32/row
    int e = g_rowptr[warp];
    const int e1 = g_rowptr[warp + 1];

    float4 acc = make_float4(0.f, 0.f, 0.f, 0.f);

    for (; e + 8 <= e1; e += 8) {
        int   s[8]; float w[8]; uint2 v[8];
        #pragma unroll
        for (int j = 0; j < 8; j++) { s[j] = g_esrc[e + j]; w[j] = g_enorm[e + j]; }
        #pragma unroll
        for (int j = 0; j < 8; j++) v[j] = __ldg(h2 + s[j] * 32 + lane);
        #pragma unroll
        for (int j = 0; j < 8; j++) {
            float2 f0 = __half22float2(*(__half2*)&v[j].x);
            float2 f1 = __half22float2(*(__half2*)&v[j].y);
            acc.x += w[j] * f0.x; acc.y += w[j] * f0.y;
            acc.z += w[j] * f1.x; acc.w += w[j] * f1.y;
        }
    }
    for (; e < e1; e++) {
        int s0 = g_esrc[e];
        float n0 = g_enorm[e];
        uint2 v0 = __ldg(h2 + s0 * 32 + lane);
        float2 f0 = __half22float2(*(__half2*)&v0.x);
        float2 f1 = __half22float2(*(__half2*)&v0.y);
        acc.x += n0 * f0.x; acc.y += n0 * f0.y;
        acc.z += n0 * f1.x; acc.w += n0 * f1.y;
    }

    float di = g_dinv[warp];
    float sl = di * di;
    uint2 vr = __ldg(h2 + warp * 32 + lane);
    float2 vi0 = __half22float2(*(__half2*)&vr.x);
    float2 vi1 = __half22float2(*(__half2*)&vr.y);
    float4 vb = __ldg((const float4*)b + lane);
    __half2 o0 = __floats2half2_rn(fmaxf(acc.x + sl * vi0.x + vb.x, 0.f),
                                   fmaxf(acc.y + sl * vi0.y + vb.y, 0.f));
    __half2 o1 = __floats2half2_rn(fmaxf(acc.z + sl * vi1.x + vb.z, 0.f),
                                   fmaxf(acc.w + sl * vi1.y + vb.w, 0.f));
    uint2 o;
    o.x = *(uint32_t*)&o0;
    o.y = *(uint32_t*)&o1;
    ((uint2*)out)[warp * 32 + lane] = o;
}

// ---------------- final aggregation (C=50, half input, no relu) --------------
__global__ __launch_bounds__(256) void k_agg_fin(const __half* __restrict__ h,
                                                 const float* __restrict__ b,
                                                 float* __restrict__ out, int n) {
    int warp = (blockIdx.x * blockDim.x + threadIdx.x) >> 5;
    int lane = threadIdx.x & 31;
    if (warp >= n) return;
    const int i = warp;
    int e = g_rowptr[i];
    const int e1 = g_rowptr[i + 1];
    const int f0 = lane;            // < 32
    const int f1 = lane + 32;       // < 50 for lanes 0..17

    float a0 = 0.f, a1 = 0.f;
    for (; e + 4 <= e1; e += 4) {
        int s0 = g_esrc[e], s1 = g_esrc[e + 1], s2 = g_esrc[e + 2], s3 = g_esrc[e + 3];
        float n0 = g_enorm[e], n1 = g_enorm[e + 1], n2 = g_enorm[e + 2], n3 = g_enorm[e + 3];
        const __half* p0 = h + (size_t)s0 * 64;
        const __half* p1 = h + (size_t)s1 * 64;
        const __half* p2 = h + (size_t)s2 * 64;
        const __half* p3 = h + (size_t)s3 * 64;
        a0 += n0 * __half2float(__ldg(p0 + f0));
        a0 += n1 * __half2float(__ldg(p1 + f0));
        a0 += n2 * __half2float(__ldg(p2 + f0));
        a0 += n3 * __half2float(__ldg(p3 + f0));
        if (f1 < 50) {
            a1 += n0 * __half2float(__ldg(p0 + f1));
            a1 += n1 * __half2float(__ldg(p1 + f1));
            a1 += n2 * __half2float(__ldg(p2 + f1));
            a1 += n3 * __half2float(__ldg(p3 + f1));
        }
    }
    for (; e < e1; e++) {
        int s0 = g_esrc[e];
        float n0 = g_enorm[e];
        const __half* p0 = h + (size_t)s0 * 64;
        a0 += n0 * __half2float(__ldg(p0 + f0));
        if (f1 < 50) a1 += n0 * __half2float(__ldg(p0 + f1));
    }

    float di = g_dinv[i];
    float sl = di * di;
    const __half* hi = h + (size_t)i * 64;
    out[(size_t)i * 50 + f0] = a0 + sl * __half2float(__ldg(hi + f0)) + __ldg(b + f0);
    if (f1 < 50)
        out[(size_t)i * 50 + f1] = a1 + sl * __half2float(__ldg(hi + f1)) + __ldg(b + f1);
}

// ---------------- launch ----------------
extern "C" void kernel_launch(void* const* d_in, const int* in_sizes, int n_in,
                              void* d_out, int out_size) {
    const float* x  = (const float*)d_in[0];
    const void*  ei = d_in[1];
    const float* W1 = (const float*)d_in[2];  const float* b1 = (const float*)d_in[3];
    const float* W2 = (const float*)d_in[4];  const float* b2 = (const float*)d_in[5];
    const float* W3 = (const float*)d_in[6];  const float* b3 = (const float*)d_in[7];
    const float* W4 = (const float*)d_in[8];  const float* b4 = (const float*)d_in[9];
    const float* W5 = (const float*)d_in[10]; const float* b5 = (const float*)d_in[11];

    const int N = in_sizes[0] / 384;
    const int E = in_sizes[1] / 2;

    __half *h, *y, *x16, *wt1, *wt2, *wt3, *wt4, *wt5;
    cudaGetSymbolAddress((void**)&h, g_h);
    cudaGetSymbolAddress((void**)&y, g_y);
    cudaGetSymbolAddress((void**)&x16, g_x16);
    cudaGetSymbolAddress((void**)&wt1, g_wt1);
    cudaGetSymbolAddress((void**)&wt2, g_wt2);
    cudaGetSymbolAddress((void**)&wt3, g_wt3);
    cudaGetSymbolAddress((void**)&wt4, g_wt4);
    cudaGetSymbolAddress((void**)&wt5, g_wt5);

    const int T = 256;
    const int gN = (N + T - 1) / T;
    const int gE = (E + T - 1) / T;
    const int nb = (N + 1023) / 1024;
    const int gm = (N + 127) / 128;
    const int ga = (N + 7) / 8;
    const int nx4 = N * 384 / 4;

    // dynamic smem: 3 stages * (BM + BN) rows * 40 halves * 2B
    const int smem128 = 3 * (128 + 128) * 40 * 2;   // 61440
    const int smem64  = 3 * (128 + 64) * 40 * 2;    // 46080
    cudaFuncSetAttribute(k_gemm16<384, 128, 128>,
                         cudaFuncAttributeMaxDynamicSharedMemorySize, smem128);
    cudaFuncSetAttribute(k_gemm16<128, 128, 128>,
                         cudaFuncAttributeMaxDynamicSharedMemorySize, smem128);
    cudaFuncSetAttribute(k_gemm16<128, 64, 64>,
                         cudaFuncAttributeMaxDynamicSharedMemorySize, smem64);

    // launch order keeps GEMM1 at launch index 3 (ncu capture slot)
    k_init<<<gN, T>>>(ei, E, (long long)N, N);
    k_wtrans_all<<<(106496 + 255) / 256, T>>>(W1, W2, W3, W4, W5);
    k_x16<<<(nx4 + T - 1) / T, T>>>(x, nx4);
    k_gemm16<384, 128, 128><<<gm, T, smem128>>>(x16, wt1, h, N);   // GEMM1
    k_hist<<<gE, T>>>(ei, E);
    k_scan1<<<nb, 1024>>>(N);
    k_scan2<<<1, 32>>>(nb, N);
    k_scan3<<<gN, T>>>(N);
    k_scatter<<<gE, T>>>(ei, E);

    // layer 1 aggregation (half gathers -> fp16 y)
    k_agg128<<<ga, T>>>(h, b1, y, N);
    // layers 2-4
    k_gemm16<128, 128, 128><<<gm, T, smem128>>>(y, wt2, h, N);
    k_agg128<<<ga, T>>>(h, b2, y, N);
    k_gemm16<128, 128, 128><<<gm, T, smem128>>>(y, wt3, h, N);
    k_agg128<<<ga, T>>>(h, b3, y, N);
    k_gemm16<128, 128, 128><<<gm, T, smem128>>>(y, wt4, h, N);
    k_agg128<<<ga, T>>>(h, b4, y, N);
    // layer 5: 128 -> 50 (64 padded cols, fp16), then final aggregation
    k_gemm16<128, 64, 64><<<gm, T, smem64>>>(y, wt5, h, N);
    k_agg_fin<<<ga, T>>>(h, b5, (float*)d_out, N);
}

// round 10
// speedup vs baseline: 1.9203x; 1.1321x over previous
#include <cuda_runtime.h>
#include <cuda_fp16.h>
#include <cstdint>

#define N_NODES_MAX 100000
#define N_EDGES_MAX 1600000

// ---------------- device scratch (no allocations allowed) ----------------
__device__ __half g_h[(size_t)N_NODES_MAX * 128];   // GEMM output (fp16, gathered)
__device__ __half g_y[(size_t)N_NODES_MAX * 128];   // agg output (fp16, GEMM A)
__device__ float g_dinv[N_NODES_MAX];
__device__ int   g_count[N_NODES_MAX];
__device__ int   g_fill[N_NODES_MAX];
__device__ int   g_rowptr[N_NODES_MAX + 1];
__device__ int   g_esrc[N_EDGES_MAX];
__device__ float g_enorm[N_EDGES_MAX];
__device__ int   g_bsums[256];
__device__ int   g_is32;
// transposed fp16 weights: WT[n][k]
__device__ __half g_wt1[128 * 384];
__device__ __half g_wt2[128 * 128];
__device__ __half g_wt3[128 * 128];
__device__ __half g_wt4[128 * 128];
__device__ __half g_wt5[64 * 128];

// ---------------- helpers ----------------
__device__ __forceinline__ int edge_val(const void* ei, int is32, long long idx) {
    if (is32) return ((const int*)ei)[idx];
    return (int)((const long long*)ei)[idx];
}
__device__ __forceinline__ void cp_async16(uint32_t dst, const void* src, int srcsize) {
    asm volatile("cp.async.ca.shared.global [%0], [%1], 16, %2;"
                 :: "r"(dst), "l"(src), "r"(srcsize));
}
__device__ __forceinline__ void cp_commit() { asm volatile("cp.async.commit_group;"); }
template<int N>
__device__ __forceinline__ void cp_wait() { asm volatile("cp.async.wait_group %0;" :: "n"(N)); }

__device__ __forceinline__ void ldsm_x4(uint32_t& r0, uint32_t& r1, uint32_t& r2, uint32_t& r3,
                                        uint32_t addr) {
    asm volatile("ldmatrix.sync.aligned.m8n8.x4.shared.b16 {%0,%1,%2,%3}, [%4];"
                 : "=r"(r0), "=r"(r1), "=r"(r2), "=r"(r3) : "r"(addr));
}

// ---------------- preprocessing kernels ----------------
__global__ void k_init(const void* ei, int E, long long N, int n) {
    int i = blockIdx.x * blockDim.x + threadIdx.x;
    if (i < n) { g_count[i] = 0; g_fill[i] = 0; }
    if (i == 0) {
        const long long* p = (const long long*)ei;
        int is32 = 0;
        for (int j = 0; j < 64 && j < E; j++) {
            long long v = p[j];
            if (v < 0 || v >= N) { is32 = 1; break; }
        }
        g_is32 = is32;
    }
}

__global__ void k_hist(const void* __restrict__ ei, int E) {
    int e = blockIdx.x * blockDim.x + threadIdx.x;
    if (e >= E) return;
    int is32 = g_is32;
    int d = edge_val(ei, is32, (long long)E + e);
    atomicAdd(&g_count[d], 1);
}

// scan over counts; also computes dinv (fused)
__global__ void k_scan1(int n) {
    __shared__ int s[1024];
    int t = threadIdx.x;
    int i = blockIdx.x * 1024 + t;
    int v = (i < n) ? g_count[i] : 0;
    if (i < n) g_dinv[i] = rsqrtf((float)v + 1.0f);
    s[t] = v;
    __syncthreads();
    #pragma unroll
    for (int off = 1; off < 1024; off <<= 1) {
        int x = (t >= off) ? s[t - off] : 0;
        __syncthreads();
        s[t] += x;
        __syncthreads();
    }
    if (i < n) g_rowptr[i] = s[t] - v;
    if (t == 1023) g_bsums[blockIdx.x] = s[1023];
}

// parallel block-sum scan (256 threads; nb <= 256)
__global__ void k_scan2(int nb, int n) {
    __shared__ int s[256];
    int t = threadIdx.x;
    int v = (t < nb) ? g_bsums[t] : 0;
    s[t] = v;
    __syncthreads();
    #pragma unroll
    for (int off = 1; off < 256; off <<= 1) {
        int x = (t >= off) ? s[t - off] : 0;
        __syncthreads();
        s[t] += x;
        __syncthreads();
    }
    if (t < nb) g_bsums[t] = s[t] - v;   // exclusive block offsets
    if (t == 255) g_rowptr[n] = s[255];
}

__global__ void k_scan3(int n) {
    int i = blockIdx.x * blockDim.x + threadIdx.x;
    if (i < n) g_rowptr[i] += g_bsums[i >> 10];
}

__global__ void k_scatter(const void* __restrict__ ei, int E) {
    int e = blockIdx.x * blockDim.x + threadIdx.x;
    if (e >= E) return;
    int is32 = g_is32;
    int s = edge_val(ei, is32, e);
    int d = edge_val(ei, is32, (long long)E + e);
    int pos = g_rowptr[d] + atomicAdd(&g_fill[d], 1);
    g_esrc[pos]  = s;
    g_enorm[pos] = g_dinv[s] * g_dinv[d];
}

// ---------------- all weight transposes (fp16) in one kernel ----------------
__global__ void k_wtrans_all(const float* __restrict__ W1, const float* __restrict__ W2,
                             const float* __restrict__ W3, const float* __restrict__ W4,
                             const float* __restrict__ W5) {
    int idx = blockIdx.x * 256 + threadIdx.x;
    if (idx < 49152) {                       // wt1: [128][384] from W1[384][128]
        int n = idx / 384, k = idx % 384;
        g_wt1[idx] = __float2half_rn(W1[(size_t)k * 128 + n]);
    } else if (idx < 49152 + 16384) {        // wt2
        int j = idx - 49152; int n = j / 128, k = j % 128;
        g_wt2[j] = __float2half_rn(W2[(size_t)k * 128 + n]);
    } else if (idx < 49152 + 32768) {        // wt3
        int j = idx - 49152 - 16384; int n = j / 128, k = j % 128;
        g_wt3[j] = __float2half_rn(W3[(size_t)k * 128 + n]);
    } else if (idx < 49152 + 49152) {        // wt4
        int j = idx - 49152 - 32768; int n = j / 128, k = j % 128;
        g_wt4[j] = __float2half_rn(W4[(size_t)k * 128 + n]);
    } else if (idx < 49152 + 49152 + 8192) { // wt5: [64][128] from W5[128][50]
        int j = idx - 49152 - 49152; int n = j / 128, k = j % 128;
        g_wt5[j] = (n < 50) ? __float2half_rn(W5[(size_t)k * 50 + n]) : __float2half_rn(0.f);
    }
}

// ---------------- fp16 tensor-core GEMM --------------------------------------
// C[M, SC] = A[M, KT] @ WT^T  (WT fp16 [BN][KT] n-major)
// CVT=false: A fp16 row-major, cp.async 3-stage.
// CVT=true : A fp32 row-major, LDG+cvt+STS 2-stage (folds fp32->fp16 in).
// mma m16n8k16 f16, fp32 accumulate; fp16 output via smem-staged coalesced STG.
template<int KT, int BN, int SC, bool CVT>
__global__ __launch_bounds__(256, 2) void k_gemm16(const void* __restrict__ Ain,
                                                   const __half* __restrict__ WT,
                                                   __half* __restrict__ C, int M) {
    constexpr int BM = 128, BKH = 32;       // k-tile in halves
    constexpr int WTN = BN / 4;             // 32 or 16
    constexpr int NTL = WTN / 8;            // 4 or 2
    constexpr int LDR = BKH + 8;            // 40 halves = 80B rows
    constexpr int NK  = KT / BKH;
    constexpr int AST = BM * LDR;           // halves per A stage
    constexpr int WST = BN * LDR;
    constexpr int NSTAGE = CVT ? 2 : 3;
    constexpr int WCH = BN * 4 / 256;       // W cp.async chunks/thread (2 or 1)

    extern __shared__ __half smem[];
    __half* Abase = smem;
    __half* Wbase = smem + NSTAGE * AST;

    const int tid = threadIdx.x;
    const int wid = tid >> 5;
    const int lane = tid & 31;
    const int g = lane >> 2;
    const int t = lane & 3;
    const int warp_m = wid >> 2;            // 0..1
    const int warp_n = wid & 3;             // 0..3
    const int row0 = blockIdx.x * BM;

    const uint32_t sA = (uint32_t)__cvta_generic_to_shared(Abase);
    const uint32_t sW = (uint32_t)__cvta_generic_to_shared(Wbase);

    float acc[4][NTL][4];
    #pragma unroll
    for (int i = 0; i < 4; i++)
        #pragma unroll
        for (int j = 0; j < NTL; j++)
            #pragma unroll
            for (int r = 0; r < 4; r++) acc[i][j][r] = 0.f;

    auto cpW = [&](int i, int st) {
        const int kb = i * BKH;
        #pragma unroll
        for (int j = 0; j < WCH; j++) {
            int idx = tid + j * 256;
            int n = idx >> 2, ch = idx & 3;
            const __half* src = WT + (size_t)n * KT + kb + ch * 8;
            uint32_t dst = sW + (uint32_t)((st * WST + n * LDR + ch * 8) * 2);
            cp_async16(dst, src, 16);
        }
    };

    auto compute = [&](int st) {
        #pragma unroll
        for (int ks = 0; ks < 2; ks++) {
            const int k16 = ks * 16;
            uint32_t bf[NTL][2];
            #pragma unroll
            for (int np = 0; np < NTL / 2; np++) {
                int n0 = warp_n * WTN + np * 16;
                uint32_t ad = sW + (uint32_t)(((st * WST) +
                              (n0 + (lane & 7) + ((lane >> 4) & 1) * 8) * LDR +
                              k16 + ((lane >> 3) & 1) * 8) * 2);
                ldsm_x4(bf[2 * np][0], bf[2 * np][1], bf[2 * np + 1][0], bf[2 * np + 1][1], ad);
            }
            #pragma unroll
            for (int mt = 0; mt < 4; mt++) {
                int mb = warp_m * 64 + mt * 16;
                uint32_t ad = sA + (uint32_t)(((st * AST) +
                              (mb + (lane & 15)) * LDR + k16 + (lane >> 4) * 8) * 2);
                uint32_t a0, a1, a2, a3;
                ldsm_x4(a0, a1, a2, a3, ad);
                #pragma unroll
                for (int nt = 0; nt < NTL; nt++) {
                    asm volatile(
                        "mma.sync.aligned.m16n8k16.row.col.f32.f16.f16.f32 "
                        "{%0,%1,%2,%3}, {%4,%5,%6,%7}, {%8,%9}, {%0,%1,%2,%3};"
                        : "+f"(acc[mt][nt][0]), "+f"(acc[mt][nt][1]),
                          "+f"(acc[mt][nt][2]), "+f"(acc[mt][nt][3])
                        : "r"(a0), "r"(a1), "r"(a2), "r"(a3),
                          "r"(bf[nt][0]), "r"(bf[nt][1]));
                }
            }
        }
    };

    if constexpr (CVT) {
        // ---- fp32 A: LDG float4 -> cvt -> STS, 2-stage double buffer ----
        const float* A32 = (const float*)Ain;
        float4 pa[4];
        auto ldA = [&](int i) {
            const int kb = i * BKH;
            #pragma unroll
            for (int j = 0; j < 4; j++) {
                int idx = tid + j * 256;
                int r = idx >> 3, c4 = idx & 7;
                int grow = row0 + r;
                pa[j] = (grow < M)
                    ? __ldg((const float4*)(A32 + (size_t)grow * KT + kb + c4 * 4))
                    : make_float4(0.f, 0.f, 0.f, 0.f);
            }
        };
        auto stsA = [&](int st) {
            #pragma unroll
            for (int j = 0; j < 4; j++) {
                int idx = tid + j * 256;
                int r = idx >> 3, c4 = idx & 7;
                __half2 h0 = __floats2half2_rn(pa[j].x, pa[j].y);
                __half2 h1 = __floats2half2_rn(pa[j].z, pa[j].w);
                uint2 u;
                u.x = *(uint32_t*)&h0;
                u.y = *(uint32_t*)&h1;
                *(uint2*)(Abase + st * AST + r * LDR + c4 * 4) = u;
            }
        };

        ldA(0);
        cpW(0, 0); cp_commit();
        stsA(0);
        ldA(1);
        cpW(1, 1); cp_commit();
        cp_wait<1>();
        __syncthreads();

        for (int i = 0; i < NK; i++) {
            const int st = i & 1;
            compute(st);
            __syncthreads();                       // stage st fully consumed
            if (i + 1 < NK) stsA((i + 1) & 1);     // A(i+1) regs -> other stage
            if (i + 2 < NK) { ldA(i + 2); cpW(i + 2, st); }
            cp_commit();
            cp_wait<1>();
            __syncthreads();
        }
    } else {
        // ---- fp16 A: cp.async 3-stage ring ----
        const __half* A16 = (const __half*)Ain;
        auto cpA = [&](int i, int st) {
            const int kb = i * BKH;
            #pragma unroll
            for (int j = 0; j < 2; j++) {
                int idx = tid + j * 256;
                int r = idx >> 2, ch = idx & 3;
                int grow = row0 + r;
                const __half* src = A16 + (size_t)grow * KT + kb + ch * 8;
                uint32_t dst = sA + (uint32_t)((st * AST + r * LDR + ch * 8) * 2);
                cp_async16(dst, src, grow < M ? 16 : 0);
            }
        };

        cpA(0, 0); cpW(0, 0); cp_commit();
        cpA(1, 1); cpW(1, 1); cp_commit();

        for (int i = 0; i < NK; i++) {
            const int st = i % 3;
            cp_wait<1>();
            __syncthreads();
            compute(st);
            if (i + 2 < NK) { cpA(i + 2, (i + 2) % 3); cpW(i + 2, (i + 2) % 3); }
            cp_commit();
        }
    }

    // ---- epilogue: stage C in smem, then coalesced STG.128 ----
    __syncthreads();                               // smem stages free for reuse
    constexpr int CLDR = BN + 8;
    __half* Cs = smem;
    #pragma unroll
    for (int mt = 0; mt < 4; mt++) {
        int rl = warp_m * 64 + mt * 16 + g;
        #pragma unroll
        for (int nt = 0; nt < NTL; nt++) {
            int col = warp_n * WTN + nt * 8 + t * 2;
            *(__half2*)(Cs + rl * CLDR + col) =
                __floats2half2_rn(acc[mt][nt][0], acc[mt][nt][1]);
            *(__half2*)(Cs + (rl + 8) * CLDR + col) =
                __floats2half2_rn(acc[mt][nt][2], acc[mt][nt][3]);
        }
    }
    __syncthreads();
    constexpr int CH8 = BN / 8;                    // 16B chunks per row
    #pragma unroll
    for (int j = 0; j < (BM * CH8) / 256; j++) {
        int idx = tid + j * 256;
        int r = idx / CH8, c8 = idx % CH8;
        int grow = row0 + r;
        if (grow < M)
            *(uint4*)(C + (size_t)grow * SC + c8 * 8) = *(uint4*)(Cs + r * CLDR + c8 * 8);
    }
}

// ---------------- aggregation (C=128): warp per node, half in/half out -------
__global__ __launch_bounds__(256) void k_agg128(const __half* __restrict__ hin,
                                                const float* __restrict__ b,
                                                __half* __restrict__ out, int n) {
    int warp = (blockIdx.x * blockDim.x + threadIdx.x) >> 5;
    int lane = threadIdx.x & 31;
    if (warp >= n) return;
    const uint2* __restrict__ h2 = (const uint2*)hin;   // 4 halves per uint2; 32/row
    int e = g_rowptr[warp];
    const int e1 = g_rowptr[warp + 1];

    float4 acc = make_float4(0.f, 0.f, 0.f, 0.f);

    for (; e + 8 <= e1; e += 8) {
        int   s[8]; float w[8]; uint2 v[8];
        #pragma unroll
        for (int j = 0; j < 8; j++) { s[j] = g_esrc[e + j]; w[j] = g_enorm[e + j]; }
        #pragma unroll
        for (int j = 0; j < 8; j++) v[j] = __ldg(h2 + s[j] * 32 + lane);
        #pragma unroll
        for (int j = 0; j < 8; j++) {
            float2 f0 = __half22float2(*(__half2*)&v[j].x);
            float2 f1 = __half22float2(*(__half2*)&v[j].y);
            acc.x += w[j] * f0.x; acc.y += w[j] * f0.y;
            acc.z += w[j] * f1.x; acc.w += w[j] * f1.y;
        }
    }
    for (; e < e1; e++) {
        int s0 = g_esrc[e];
        float n0 = g_enorm[e];
        uint2 v0 = __ldg(h2 + s0 * 32 + lane);
        float2 f0 = __half22float2(*(__half2*)&v0.x);
        float2 f1 = __half22float2(*(__half2*)&v0.y);
        acc.x += n0 * f0.x; acc.y += n0 * f0.y;
        acc.z += n0 * f1.x; acc.w += n0 * f1.y;
    }

    float di = g_dinv[warp];
    float sl = di * di;
    uint2 vr = __ldg(h2 + warp * 32 + lane);
    float2 vi0 = __half22float2(*(__half2*)&vr.x);
    float2 vi1 = __half22float2(*(__half2*)&vr.y);
    float4 vb = __ldg((const float4*)b + lane);
    __half2 o0 = __floats2half2_rn(fmaxf(acc.x + sl * vi0.x + vb.x, 0.f),
                                   fmaxf(acc.y + sl * vi0.y + vb.y, 0.f));
    __half2 o1 = __floats2half2_rn(fmaxf(acc.z + sl * vi1.x + vb.z, 0.f),
                                   fmaxf(acc.w + sl * vi1.y + vb.w, 0.f));
    uint2 o;
    o.x = *(uint32_t*)&o0;
    o.y = *(uint32_t*)&o1;
    ((uint2*)out)[warp * 32 + lane] = o;
}

// ---------------- final aggregation (C=50, half input, no relu) --------------
__global__ __launch_bounds__(256) void k_agg_fin(const __half* __restrict__ h,
                                                 const float* __restrict__ b,
                                                 float* __restrict__ out, int n) {
    int warp = (blockIdx.x * blockDim.x + threadIdx.x) >> 5;
    int lane = threadIdx.x & 31;
    if (warp >= n) return;
    const int i = warp;
    int e = g_rowptr[i];
    const int e1 = g_rowptr[i + 1];
    const int f0 = lane;            // < 32
    const int f1 = lane + 32;       // < 50 for lanes 0..17

    float a0 = 0.f, a1 = 0.f;
    for (; e + 4 <= e1; e += 4) {
        int s0 = g_esrc[e], s1 = g_esrc[e + 1], s2 = g_esrc[e + 2], s3 = g_esrc[e + 3];
        float n0 = g_enorm[e], n1 = g_enorm[e + 1], n2 = g_enorm[e + 2], n3 = g_enorm[e + 3];
        const __half* p0 = h + (size_t)s0 * 64;
        const __half* p1 = h + (size_t)s1 * 64;
        const __half* p2 = h + (size_t)s2 * 64;
        const __half* p3 = h + (size_t)s3 * 64;
        a0 += n0 * __half2float(__ldg(p0 + f0));
        a0 += n1 * __half2float(__ldg(p1 + f0));
        a0 += n2 * __half2float(__ldg(p2 + f0));
        a0 += n3 * __half2float(__ldg(p3 + f0));
        if (f1 < 50) {
            a1 += n0 * __half2float(__ldg(p0 + f1));
            a1 += n1 * __half2float(__ldg(p1 + f1));
            a1 += n2 * __half2float(__ldg(p2 + f1));
            a1 += n3 * __half2float(__ldg(p3 + f1));
        }
    }
    for (; e < e1; e++) {
        int s0 = g_esrc[e];
        float n0 = g_enorm[e];
        const __half* p0 = h + (size_t)s0 * 64;
        a0 += n0 * __half2float(__ldg(p0 + f0));
        if (f1 < 50) a1 += n0 * __half2float(__ldg(p0 + f1));
    }

    float di = g_dinv[i];
    float sl = di * di;
    const __half* hi = h + (size_t)i * 64;
    out[(size_t)i * 50 + f0] = a0 + sl * __half2float(__ldg(hi + f0)) + __ldg(b + f0);
    if (f1 < 50)
        out[(size_t)i * 50 + f1] = a1 + sl * __half2float(__ldg(hi + f1)) + __ldg(b + f1);
}

// ---------------- launch ----------------
extern "C" void kernel_launch(void* const* d_in, const int* in_sizes, int n_in,
                              void* d_out, int out_size) {
    const float* x  = (const float*)d_in[0];
    const void*  ei = d_in[1];
    const float* W1 = (const float*)d_in[2];  const float* b1 = (const float*)d_in[3];
    const float* W2 = (const float*)d_in[4];  const float* b2 = (const float*)d_in[5];
    const float* W3 = (const float*)d_in[6];  const float* b3 = (const float*)d_in[7];
    const float* W4 = (const float*)d_in[8];  const float* b4 = (const float*)d_in[9];
    const float* W5 = (const float*)d_in[10]; const float* b5 = (const float*)d_in[11];

    const int N = in_sizes[0] / 384;
    const int E = in_sizes[1] / 2;

    __half *h, *y, *wt1, *wt2, *wt3, *wt4, *wt5;
    cudaGetSymbolAddress((void**)&h, g_h);
    cudaGetSymbolAddress((void**)&y, g_y);
    cudaGetSymbolAddress((void**)&wt1, g_wt1);
    cudaGetSymbolAddress((void**)&wt2, g_wt2);
    cudaGetSymbolAddress((void**)&wt3, g_wt3);
    cudaGetSymbolAddress((void**)&wt4, g_wt4);
    cudaGetSymbolAddress((void**)&wt5, g_wt5);

    const int T = 256;
    const int gN = (N + T - 1) / T;
    const int gE = (E + T - 1) / T;
    const int nb = (N + 1023) / 1024;
    const int gm = (N + 127) / 128;
    const int ga = (N + 7) / 8;

    // dynamic smem (halves*2B): CVT: 2*(AST+WST); else 3*(AST+WST); epi fits inside
    const int smemCVT = 2 * (128 + 128) * 40 * 2;   // 40960
    const int smem128 = 3 * (128 + 128) * 40 * 2;   // 61440
    const int smem64  = 3 * (128 + 64) * 40 * 2;    // 46080
    cudaFuncSetAttribute(k_gemm16<384, 128, 128, true>,
                         cudaFuncAttributeMaxDynamicSharedMemorySize, smemCVT);
    cudaFuncSetAttribute(k_gemm16<128, 128, 128, false>,
                         cudaFuncAttributeMaxDynamicSharedMemorySize, smem128);
    cudaFuncSetAttribute(k_gemm16<128, 64, 64, false>,
                         cudaFuncAttributeMaxDynamicSharedMemorySize, smem64);

    // launch order keeps GEMM1 at launch index 3 (ncu capture slot)
    k_init<<<gN, T>>>(ei, E, (long long)N, N);
    k_wtrans_all<<<(106496 + 255) / 256, T>>>(W1, W2, W3, W4, W5);
    k_hist<<<gE, T>>>(ei, E);
    k_gemm16<384, 128, 128, true><<<gm, T, smemCVT>>>(x, wt1, h, N);   // GEMM1 (+cvt)
    k_scan1<<<nb, 1024>>>(N);
    k_scan2<<<1, 256>>>(nb, N);
    k_scan3<<<gN, T>>>(N);
    k_scatter<<<gE, T>>>(ei, E);

    // layer 1 aggregation (half gathers -> fp16 y)
    k_agg128<<<ga, T>>>(h, b1, y, N);
    // layers 2-4
    k_gemm16<128, 128, 128, false><<<gm, T, smem128>>>(y, wt2, h, N);
    k_agg128<<<ga, T>>>(h, b2, y, N);
    k_gemm16<128, 128, 128, false><<<gm, T, smem128>>>(y, wt3, h, N);
    k_agg128<<<ga, T>>>(h, b3, y, N);
    k_gemm16<128, 128, 128, false><<<gm, T, smem128>>>(y, wt4, h, N);
    k_agg128<<<ga, T>>>(h, b4, y, N);
    // layer 5: 128 -> 50 (64 padded cols, fp16), then final aggregation
    k_gemm16<128, 64, 64, false><<<gm, T, smem64>>>(y, wt5, h, N);
    k_agg_fin<<<ga, T>>>(h, b5, (float*)d_out, N);
}